// round 4
// baseline (speedup 1.0000x reference)
#include <cuda_runtime.h>

// Problem constants (fixed by the reference).
#define NB 4096      // bodies
#define KB 16384     // broad-phase keep count
#define KE 4096      // exact-phase keep count
#define TPB 1024     // single fused block
#define BPT (NB / TPB)      // 4 bodies (rows) per thread, contiguous => row-major order
// Spatial grid: rsum <= 3.0 (radii in [0.5,1.5]); cell 3.25 guarantees any
// AABB-overlapping pair sits in adjacent cells, incl. under edge clamping.
#define NC 128
#define NCELLS (NC * NC)
#define CPT (NCELLS / TPB)  // 16 cells per thread
#define CELL 3.25f
#define ORG  (-208.0f)
#define CAP  32      // per-row gathered candidate cap (fallback: brute scan)

// dynamic SMEM layout
#define SB_OFF 0                       // float4 s_body[NB]        : 65536 B
#define ST_OFF 65536                   // int s_start[NCELLS + 1]  : 65540 B
#define CU_OFF (65536 + 65540)         // int s_cur[NCELLS]        : 65536 B
#define SMEM_BYTES (CU_OFF + 65536)    // 196612 B

// ---- device scratch (no allocations allowed) ----
__device__ int   g_winner[NB];   // encoded (phase*KE + slot), -1 = untouched
__device__ float g_evx[KE];
__device__ float g_evy[KE];

// Pinned-rounding pair predicate — bit-identical at every use site (ranks are
// recomputed independently in count / rescan / emit and must agree).
__device__ __forceinline__ void pair_flags(float xi, float yi, float ri,
                                           float xj, float yj, float rj,
                                           bool self, bool& A, bool& P) {
    float dx = fabsf(__fsub_rn(xi, xj));
    float dy = fabsf(__fsub_rn(yi, yj));
    float rs = __fadd_rn(ri, rj);
    A = (dx <= rs) & (dy <= rs) & (!self);
    float d2 = __fadd_rn(__fmaf_rn(dy, dy, __fmul_rn(dx, dx)), 1e-12f);
    P = A & (d2 < __fmul_rn(rs, rs));   // pen>0 <=> rs^2 > d^2+eps (monotone)
}

__device__ __forceinline__ void emit_pair(int slot, int i, int j,
                                          float xi, float yi, float ri,
                                          float xj, float yj, float rj) {
    float dvx = __fsub_rn(xi, xj);
    float dvy = __fsub_rn(yi, yj);
    float rs  = __fadd_rn(ri, rj);
    float d2  = __fadd_rn(__fmaf_rn(dvy, dvy, __fmul_rn(dvx, dvx)), 1e-12f);
    float dist = __fsqrt_rn(d2);
    float s = __fdiv_rn(__fsub_rn(rs, dist), dist);     // pen_depth / dist
    __stcg(&g_evx[slot], __fmul_rn(dvx, s));
    __stcg(&g_evy[slot], __fmul_rn(dvy, s));
    atomicMax(&g_winner[i], slot);        // i-phase priority
    atomicMax(&g_winner[j], slot + KE);   // j-phase (applied after all i's)
}

// Block-wide exclusive scan over 1024 ints. Contains __syncthreads:
// must be reached by all threads uniformly.
__device__ __forceinline__ int scan1024(int v, int* sh32, int t) {
    int lane = t & 31, w = t >> 5;
    int x = v;
    #pragma unroll
    for (int d = 1; d < 32; d <<= 1) {
        int y = __shfl_up_sync(0xffffffffu, x, d);
        if (lane >= d) x += y;
    }
    if (lane == 31) sh32[w] = x;
    __syncthreads();
    if (w == 0) {
        int s = sh32[lane];
        int acc = s;
        #pragma unroll
        for (int d = 1; d < 32; d <<= 1) {
            int y = __shfl_up_sync(0xffffffffu, acc, d);
            if (lane >= d) acc += y;
        }
        sh32[lane] = acc - s;   // exclusive warp base
    }
    __syncthreads();
    int r = sh32[w] + x - v;
    __syncthreads();
    return r;
}

// neighbor-range iteration: 3 contiguous spans of the cell-sorted body list.
#define FOR_NEI(cell, ...)                                          \
    {                                                               \
        int cx_ = (cell) & (NC - 1), cy_ = (cell) >> 7;             \
        int cx0_ = max(cx_ - 1, 0), cx1_ = min(cx_ + 1, NC - 1);    \
        int cy0_ = max(cy_ - 1, 0), cy1_ = min(cy_ + 1, NC - 1);    \
        for (int yy_ = cy0_; yy_ <= cy1_; yy_++) {                  \
            int s_ = s_start[yy_ * NC + cx0_];                      \
            int e_ = s_start[yy_ * NC + cx1_ + 1];                  \
            for (int k_ = s_; k_ < e_; k_++) { __VA_ARGS__ }        \
        }                                                           \
    }

__global__ void __launch_bounds__(TPB, 1)
k_fused(const float* __restrict__ pos, const float* __restrict__ rad,
        float* __restrict__ out) {
    extern __shared__ char smem[];
    float4* s_body  = (float4*)(smem + SB_OFF);
    int*    s_start = (int*)(smem + ST_OFF);
    int*    s_cur   = (int*)(smem + CU_OFF);
    __shared__ int sh32[32];
    __shared__ int shProw, shPc, shAllowedP, shPrefP;

    int t = threadIdx.x;
    const float2* p2 = (const float2*)pos;

    // ---- load bodies, compute cells, init ----
    float bx[BPT], by[BPT], br[BPT];
    int   bc[BPT];
    #pragma unroll
    for (int k = 0; k < CPT; k++) s_cur[t * CPT + k] = 0;
    #pragma unroll
    for (int m = 0; m < BPT; m++) {
        int i = t * BPT + m;
        float2 p = p2[i];
        bx[m] = p.x; by[m] = p.y; br[m] = rad[i];
        int cx = (int)floorf((p.x - ORG) / CELL);
        int cy = (int)floorf((p.y - ORG) / CELL);
        cx = min(max(cx, 0), NC - 1);
        cy = min(max(cy, 0), NC - 1);
        bc[m] = cy * NC + cx;
        g_winner[i] = -1;
    }
    if (t == 0) { shProw = -1; shPc = 0; }
    __syncthreads();

    // ---- cell histogram ----
    #pragma unroll
    for (int m = 0; m < BPT; m++) atomicAdd(&s_cur[bc[m]], 1);
    __syncthreads();

    // ---- cell prefix scan -> s_start; reset s_cur = start ----
    {
        int cnt[CPT];
        int csum = 0;
        #pragma unroll
        for (int k = 0; k < CPT; k++) { cnt[k] = s_cur[t * CPT + k]; csum += cnt[k]; }
        int run = scan1024(csum, sh32, t);
        #pragma unroll
        for (int k = 0; k < CPT; k++) {
            s_start[t * CPT + k] = run;
            run += cnt[k];
        }
        if (t == TPB - 1) s_start[NCELLS] = run;   // == NB
        __syncthreads();
        #pragma unroll
        for (int k = 0; k < CPT; k++) s_cur[t * CPT + k] = s_start[t * CPT + k];
        __syncthreads();
    }

    // ---- scatter bodies into cell-sorted list ----
    #pragma unroll
    for (int m = 0; m < BPT; m++) {
        int slot = atomicAdd(&s_cur[bc[m]], 1);
        s_body[slot] = make_float4(bx[m], by[m], br[m], __int_as_float(t * BPT + m));
    }
    __syncthreads();

    // ---- per-row A / P counts from the grid ----
    int cA[BPT], cP[BPT];
    #pragma unroll
    for (int m = 0; m < BPT; m++) {
        int i = t * BPT + m;
        int ca = 0, cp = 0;
        FOR_NEI(bc[m],
            float4 b = s_body[k_];
            int j = __float_as_int(b.w);
            bool A; bool P;
            pair_flags(bx[m], by[m], br[m], b.x, b.y, b.z, j == i, A, P);
            ca += A; cp += P;
        )
        cA[m] = ca; cP[m] = cp;
    }

    // ---- broad prefix + cutoff ----
    int sumA = 0;
    #pragma unroll
    for (int m = 0; m < BPT; m++) sumA += cA[m];
    int base = scan1024(sumA, sh32, t);

    int allowed[BPT];
    {
        int pref = base;
        #pragma unroll
        for (int m = 0; m < BPT; m++) {
            int a = KB - pref;
            if (a < 0) a = 0;
            if (a > cA[m]) a = cA[m];
            allowed[m] = a;
            if (pref < KB && pref + cA[m] > KB) {   // unique partial row
                shProw = t * BPT + m;
                shAllowedP = a;
            }
            pref += cA[m];
        }
    }
    __syncthreads();

    int prow = shProw;
    int allowedP = shAllowedP;
    unsigned mA = 0, mP = 0;
    int baseA = 0;
    if (prow >= 0) {   // uniform branch — scan1024 inside is safe
        // brute-force ordered rescan of the single partial row
        float2 pp = p2[prow];
        float rp = rad[prow];
        int j0 = t * BPT;
        #pragma unroll
        for (int m = 0; m < BPT; m++) {
            int j = j0 + m;
            float2 pj = p2[j];
            bool A; bool P;
            pair_flags(pp.x, pp.y, rp, pj.x, pj.y, rad[j], j == prow, A, P);
            mA |= (unsigned)A << m;
            mP |= (unsigned)P << m;
        }
        baseA = scan1024(__popc(mA), sh32, t);
        int cnt = 0;
        #pragma unroll
        for (int m = 0; m < BPT; m++) {
            if ((mP >> m) & 1u) {
                int ar = baseA + __popc(mA & ((1u << m) - 1u));
                if (ar < allowedP) cnt++;
            }
        }
        cnt = __reduce_add_sync(0xffffffffu, cnt);
        if ((t & 31) == 0) atomicAdd(&shPc, cnt);
        __syncthreads();
    }
    int pc = (prow >= 0) ? shPc : 0;

    // ---- exact-candidate exclusive prefix per row ----
    int prefE[BPT];
    {
        int cC[BPT];
        int sumC = 0;
        int pref = base;
        #pragma unroll
        for (int m = 0; m < BPT; m++) {
            int c;
            if (pref + cA[m] <= KB)      c = cP[m];   // fully under cutoff
            else if (pref >= KB)         c = 0;       // fully beyond
            else                         c = pc;      // the partial row
            cC[m] = c;
            sumC += c;
            pref += cA[m];
        }
        int runC = scan1024(sumC, sh32, t);
        #pragma unroll
        for (int m = 0; m < BPT; m++) {
            prefE[m] = runC;
            runC += cC[m];
        }
        if (prow >= 0 && (prow >> 2) == t) shPrefP = prefE[prow & 3];
        __syncthreads();
    }

    // ---- emit partial row (block-parallel, ordered) ----
    if (prow >= 0) {
        unsigned mC = 0;
        #pragma unroll
        for (int m = 0; m < BPT; m++) {
            if ((mP >> m) & 1u) {
                int ar = baseA + __popc(mA & ((1u << m) - 1u));
                if (ar < allowedP) mC |= 1u << m;
            }
        }
        int slotBase = shPrefP + scan1024(__popc(mC), sh32, t);
        float2 pp = p2[prow];
        float rp = rad[prow];
        unsigned mm = mC;
        int j0 = t * BPT;
        while (mm) {
            int m = __ffs(mm) - 1;
            mm &= mm - 1;
            int slot = slotBase++;
            if (slot < KE) {
                int j = j0 + m;
                float2 pj = p2[j];
                emit_pair(slot, prow, j, pp.x, pp.y, rp, pj.x, pj.y, rad[j]);
            }
        }
    }

    // ---- emit regular rows ----
    #pragma unroll
    for (int m = 0; m < BPT; m++) {
        int i = t * BPT + m;
        if (i == prow) continue;
        if (allowed[m] == 0) continue;       // beyond cutoff or empty
        int baseE = prefE[m];
        if (baseE >= KE) continue;
        if (cP[m] == 0) continue;
        // here: non-partial, allowed>0  =>  allowed == cA[m], all P-hits allowed
        if (cP[m] <= CAP) {
            int jl[CAP];
            int k = 0;
            FOR_NEI(bc[m],
                float4 b = s_body[k_];
                int j = __float_as_int(b.w);
                bool A; bool P;
                pair_flags(bx[m], by[m], br[m], b.x, b.y, b.z, j == i, A, P);
                if (P) jl[k++] = j;
            )
            // sort ascending j -> row-major within-row order
            for (int a = 1; a < k; a++) {
                int v = jl[a];
                int b = a - 1;
                while (b >= 0 && jl[b] > v) { jl[b + 1] = jl[b]; b--; }
                jl[b + 1] = v;
            }
            for (int a = 0; a < k; a++) {
                int slot = baseE + a;
                if (slot >= KE) break;
                int j = jl[a];
                float2 pj = p2[j];
                emit_pair(slot, i, j, bx[m], by[m], br[m], pj.x, pj.y, rad[j]);
            }
        } else {
            // rare overflow: brute-force ordered scan
            int rank = 0;
            for (int j = 0; j < NB; j++) {
                float2 pj = p2[j];
                float rj = rad[j];
                bool A; bool P;
                pair_flags(bx[m], by[m], br[m], pj.x, pj.y, rj, j == i, A, P);
                if (P) {
                    int slot = baseE + rank;
                    rank++;
                    if (slot < KE)
                        emit_pair(slot, i, j, bx[m], by[m], br[m], pj.x, pj.y, rj);
                }
            }
        }
    }
    __syncthreads();

    // ---- resolve (last-write-wins via encoded priority) ----
    #pragma unroll
    for (int m = 0; m < BPT; m++) {
        int i = t * BPT + m;
        float x = bx[m], y = by[m];
        int w = __ldcg(&g_winner[i]);
        if (w >= KE) {
            int k = w - KE;
            x = __fsub_rn(x, __fmul_rn(0.5f, __ldcg(&g_evx[k])));
            y = __fsub_rn(y, __fmul_rn(0.5f, __ldcg(&g_evy[k])));
        } else if (w >= 0) {
            x = __fadd_rn(x, __fmul_rn(0.5f, __ldcg(&g_evx[w])));
            y = __fadd_rn(y, __fmul_rn(0.5f, __ldcg(&g_evy[w])));
        }
        out[2 * i]     = x;
        out[2 * i + 1] = y;
    }
}

extern "C" void kernel_launch(void* const* d_in, const int* in_sizes, int n_in,
                              void* d_out, int out_size) {
    const float* pos;
    const float* rad;
    if (in_sizes[0] == 2 * NB) { pos = (const float*)d_in[0]; rad = (const float*)d_in[1]; }
    else                       { pos = (const float*)d_in[1]; rad = (const float*)d_in[0]; }
    float* out = (float*)d_out;

    static bool attr_set = false;
    if (!attr_set) {
        cudaFuncSetAttribute(k_fused, cudaFuncAttributeMaxDynamicSharedMemorySize,
                             SMEM_BYTES);
        attr_set = true;
    }
    k_fused<<<1, TPB, SMEM_BYTES>>>(pos, rad, out);
}

// round 5
// speedup vs baseline: 3.5520x; 3.5520x over previous
#include <cuda_runtime.h>

// Problem constants (fixed by the reference).
#define NB 4096      // bodies
#define KB 16384     // broad-phase keep count
#define KE 4096      // exact-phase keep count

// Spatial grid: rsum <= 3.0 (radii in [0.5,1.5]); cell 3.25 guarantees any
// AABB-overlapping pair sits in adjacent cells, incl. under edge clamping.
#define NC 128
#define NCELLS (NC * NC)
#define CELL 3.25f
#define ORG  (-208.0f)
#define CAP  64        // per-row gathered candidate cap (fallback: warp brute scan)
#define FULLM 0xffffffffu

// ---- device scratch (no allocations allowed; all states self-restoring) ----
__device__ int    g_cellCnt[NCELLS];     // zero-init; k_build re-zeros after use
__device__ int    g_cellStart[NCELLS + 1];
__device__ int    g_bodyCell[NB];
__device__ float4 g_sbody[NB];           // cell-sorted (x, y, r, bitcast(idx))
__device__ int    g_cntA[NB];
__device__ int    g_cntP[NB];
__device__ int    g_allowedRow[NB];
__device__ int    g_prefE[NB];
__device__ int    g_prow;
__device__ int    g_winner[NB];          // 0=none, slot+1=i-phase, slot+1+KE=j-phase
__device__ float  g_evx[KE];
__device__ float  g_evy[KE];

// Pinned-rounding pair predicate — bit-identical at every use site.
__device__ __forceinline__ void pair_flags(float xi, float yi, float ri,
                                           float xj, float yj, float rj,
                                           bool self, bool& A, bool& P) {
    float dx = fabsf(__fsub_rn(xi, xj));
    float dy = fabsf(__fsub_rn(yi, yj));
    float rs = __fadd_rn(ri, rj);
    A = (dx <= rs) & (dy <= rs) & (!self);
    float d2 = __fadd_rn(__fmaf_rn(dy, dy, __fmul_rn(dx, dx)), 1e-12f);
    P = A & (d2 < __fmul_rn(rs, rs));   // pen>0 <=> rs^2 > d^2+eps (monotone)
}

__device__ __forceinline__ void emit_pair(int slot, int i, int j,
                                          float xi, float yi, float ri,
                                          float xj, float yj, float rj) {
    float dvx = __fsub_rn(xi, xj);
    float dvy = __fsub_rn(yi, yj);
    float rs  = __fadd_rn(ri, rj);
    float d2  = __fadd_rn(__fmaf_rn(dvy, dvy, __fmul_rn(dvx, dvx)), 1e-12f);
    float dist = __fsqrt_rn(d2);
    float s = __fdiv_rn(__fsub_rn(rs, dist), dist);     // pen_depth / dist
    g_evx[slot] = __fmul_rn(dvx, s);
    g_evy[slot] = __fmul_rn(dvy, s);
    atomicMax(&g_winner[i], slot + 1);        // i-phase
    atomicMax(&g_winner[j], slot + 1 + KE);   // j-phase (applied after all i's)
}

// Block-wide exclusive scan over 1024 ints. Contains __syncthreads.
__device__ __forceinline__ int scan1024(int v, int* sh32, int t) {
    int lane = t & 31, w = t >> 5;
    int x = v;
    #pragma unroll
    for (int d = 1; d < 32; d <<= 1) {
        int y = __shfl_up_sync(FULLM, x, d);
        if (lane >= d) x += y;
    }
    if (lane == 31) sh32[w] = x;
    __syncthreads();
    if (w == 0) {
        int s = sh32[lane];
        int acc = s;
        #pragma unroll
        for (int d = 1; d < 32; d <<= 1) {
            int y = __shfl_up_sync(FULLM, acc, d);
            if (lane >= d) acc += y;
        }
        sh32[lane] = acc - s;
    }
    __syncthreads();
    int r = sh32[w] + x - v;
    __syncthreads();
    return r;
}

// ---- warp candidate-span helper: the 3 contiguous spans around `cell` ----
struct Spans { int s0, l0, s1, l1, s2, l2, total; };
__device__ __forceinline__ Spans get_spans(int cell) {
    Spans sp;
    int cx = cell & (NC - 1), cy = cell >> 7;
    int cx0 = max(cx - 1, 0), cx1 = min(cx + 1, NC - 1);
    int cy0 = max(cy - 1, 0), cy1 = min(cy + 1, NC - 1);
    sp.s0 = g_cellStart[cy0 * NC + cx0];
    sp.l0 = g_cellStart[cy0 * NC + cx1 + 1] - sp.s0;
    sp.s1 = 0; sp.l1 = 0; sp.s2 = 0; sp.l2 = 0;
    if (cy1 > cy0) {
        sp.s1 = g_cellStart[(cy0 + 1) * NC + cx0];
        sp.l1 = g_cellStart[(cy0 + 1) * NC + cx1 + 1] - sp.s1;
    }
    if (cy1 > cy0 + 1) {
        sp.s2 = g_cellStart[(cy0 + 2) * NC + cx0];
        sp.l2 = g_cellStart[(cy0 + 2) * NC + cx1 + 1] - sp.s2;
    }
    sp.total = sp.l0 + sp.l1 + sp.l2;
    return sp;
}
__device__ __forceinline__ int span_index(const Spans& sp, int c) {
    if (c < sp.l0) return sp.s0 + c;
    c -= sp.l0;
    if (c < sp.l1) return sp.s1 + c;
    return sp.s2 + (c - sp.l1);
}

// ------------------- K1: per-body cell + histogram --------------------------
__global__ void k_cellcount(const float* __restrict__ pos) {
    int i = blockIdx.x * blockDim.x + threadIdx.x;
    if (i >= NB) return;
    float x = pos[2 * i], y = pos[2 * i + 1];
    int cx = (int)floorf((x - ORG) / CELL);
    int cy = (int)floorf((y - ORG) / CELL);
    cx = min(max(cx, 0), NC - 1);
    cy = min(max(cy, 0), NC - 1);
    int c = cy * NC + cx;
    g_bodyCell[i] = c;
    atomicAdd(&g_cellCnt[c], 1);
}

// --------- K2 (1 block, 1024 thr): cell prefix + scatter (+ cnt reset) ------
__global__ void __launch_bounds__(1024, 1)
k_build(const float* __restrict__ pos, const float* __restrict__ rad) {
    extern __shared__ int s_cur[];          // NCELLS ints (64 KB)
    __shared__ int sh32[32];
    int t = threadIdx.x;
    const int CPT = NCELLS / 1024;          // 16 cells/thread

    int cnt[CPT];
    int csum = 0;
    #pragma unroll
    for (int k = 0; k < CPT; k++) {
        cnt[k] = g_cellCnt[t * CPT + k];
        g_cellCnt[t * CPT + k] = 0;         // restore zero for next run
        csum += cnt[k];
    }
    int run = scan1024(csum, sh32, t);
    #pragma unroll
    for (int k = 0; k < CPT; k++) {
        g_cellStart[t * CPT + k] = run;
        s_cur[t * CPT + k] = run;
        run += cnt[k];
    }
    if (t == 1023) g_cellStart[NCELLS] = run;   // == NB
    __syncthreads();

    const float2* p2 = (const float2*)pos;
    #pragma unroll
    for (int m = 0; m < NB / 1024; m++) {
        int i = t * (NB / 1024) + m;
        int c = g_bodyCell[i];
        int slot = atomicAdd(&s_cur[c], 1);
        float2 p = p2[i];
        g_sbody[slot] = make_float4(p.x, p.y, rad[i], __int_as_float(i));
    }
}

// ------------------- K3: warp-per-body A/P counts ----------------------------
__global__ void __launch_bounds__(256)
k_rowcount(const float* __restrict__ pos, const float* __restrict__ rad) {
    int gid  = blockIdx.x * blockDim.x + threadIdx.x;
    int i    = gid >> 5;
    int lane = gid & 31;
    if (i >= NB) return;
    float xi = pos[2 * i], yi = pos[2 * i + 1], ri = rad[i];
    Spans sp = get_spans(g_bodyCell[i]);
    int ca = 0, cp = 0;
    for (int base = 0; base < sp.total; base += 32) {
        int c = base + lane;
        bool val = c < sp.total;
        bool A = false, P = false;
        if (val) {
            float4 b = g_sbody[span_index(sp, c)];
            int j = __float_as_int(b.w);
            pair_flags(xi, yi, ri, b.x, b.y, b.z, j == i, A, P);
        }
        ca += __popc(__ballot_sync(FULLM, A));
        cp += __popc(__ballot_sync(FULLM, P));
    }
    if (lane == 0) { g_cntA[i] = ca; g_cntP[i] = cp; }
}

// ---- K4 (1 block, 1024 thr): broad prefix + cutoff + exact prefix + partial --
__global__ void __launch_bounds__(1024, 1)
k_scan(const float* __restrict__ pos, const float* __restrict__ rad) {
    __shared__ int sh32[32];
    __shared__ int shProw, shPc, shAllowedP, shPrefP;
    const int BPT = NB / 1024;   // 4 rows per thread
    int t = threadIdx.x;
    int r0 = t * BPT;
    const float2* p2 = (const float2*)pos;

    int cA[BPT], cP[BPT];
    int sum = 0;
    #pragma unroll
    for (int m = 0; m < BPT; m++) {
        cA[m] = g_cntA[r0 + m];
        cP[m] = g_cntP[r0 + m];
        sum += cA[m];
    }
    if (t == 0) { shProw = -1; shPc = 0; shAllowedP = 0; }
    int base = scan1024(sum, sh32, t);   // internal syncs publish the init

    int pref = base;
    #pragma unroll
    for (int m = 0; m < BPT; m++) {
        int i = r0 + m;
        int a = KB - pref;
        if (a < 0) a = 0;
        if (a > cA[m]) a = cA[m];
        g_allowedRow[i] = a;
        if (pref < KB && pref + cA[m] > KB) { shProw = i; shAllowedP = a; }
        pref += cA[m];
    }
    __syncthreads();

    int prow = shProw;
    int allowedP = shAllowedP;
    unsigned mA = 0, mP = 0;
    int baseA = 0;
    if (prow >= 0) {   // uniform branch
        float2 pp = p2[prow];
        float rp = rad[prow];
        #pragma unroll
        for (int m = 0; m < BPT; m++) {
            int j = r0 + m;
            float2 pj = p2[j];
            bool A; bool P;
            pair_flags(pp.x, pp.y, rp, pj.x, pj.y, rad[j], j == prow, A, P);
            mA |= (unsigned)A << m;
            mP |= (unsigned)P << m;
        }
        baseA = scan1024(__popc(mA), sh32, t);
        int cnt = 0;
        #pragma unroll
        for (int m = 0; m < BPT; m++) {
            if ((mP >> m) & 1u) {
                int ar = baseA + __popc(mA & ((1u << m) - 1u));
                if (ar < allowedP) cnt++;
            }
        }
        cnt = __reduce_add_sync(FULLM, cnt);
        if ((t & 31) == 0) atomicAdd(&shPc, cnt);
        __syncthreads();
    }
    int pc = (prow >= 0) ? shPc : 0;

    // exact-candidate exclusive prefix per row
    int prefE[BPT];
    {
        int cC[BPT];
        int sumC = 0;
        pref = base;
        #pragma unroll
        for (int m = 0; m < BPT; m++) {
            int c;
            if (pref + cA[m] <= KB)      c = cP[m];
            else if (pref >= KB)         c = 0;
            else                         c = pc;
            cC[m] = c;
            sumC += c;
            pref += cA[m];
        }
        int runC = scan1024(sumC, sh32, t);
        #pragma unroll
        for (int m = 0; m < BPT; m++) {
            prefE[m] = runC;
            g_prefE[r0 + m] = runC;
            runC += cC[m];
        }
        if (prow >= 0 && (prow / BPT) == t) shPrefP = prefE[prow % BPT];
        __syncthreads();
    }
    if (t == 0) g_prow = prow;

    // emit partial row here (block-parallel, j-ordered by construction)
    if (prow >= 0) {
        unsigned mC = 0;
        #pragma unroll
        for (int m = 0; m < BPT; m++) {
            if ((mP >> m) & 1u) {
                int ar = baseA + __popc(mA & ((1u << m) - 1u));
                if (ar < allowedP) mC |= 1u << m;
            }
        }
        int slotBase = shPrefP + scan1024(__popc(mC), sh32, t);
        float2 pp = p2[prow];
        float rp = rad[prow];
        unsigned mm = mC;
        while (mm) {
            int m = __ffs(mm) - 1;
            mm &= mm - 1;
            int slot = slotBase++;
            if (slot < KE) {
                int j = r0 + m;
                float2 pj = p2[j];
                emit_pair(slot, prow, j, pp.x, pp.y, rp, pj.x, pj.y, rad[j]);
            }
        }
    }
}

// ------------------- K5: warp-per-body ordered emit ---------------------------
__global__ void __launch_bounds__(256)
k_emit(const float* __restrict__ pos, const float* __restrict__ rad) {
    __shared__ int jls[8][CAP];     // 8 warps per 256-thread block
    int gid  = blockIdx.x * blockDim.x + threadIdx.x;
    int i    = gid >> 5;
    int lane = gid & 31;
    int wib  = (threadIdx.x >> 5);
    if (i >= NB) return;
    if (i == g_prow) return;                    // handled in k_scan
    int allowed = g_allowedRow[i];
    if (allowed == 0) return;                   // beyond cutoff (or empty row)
    int baseE = g_prefE[i];
    if (baseE >= KE) return;
    int cp = g_cntP[i];
    if (cp == 0) return;
    // non-partial row with allowed > 0  =>  allowed == cA, all P-hits kept

    float xi = pos[2 * i], yi = pos[2 * i + 1], ri = rad[i];

    if (cp <= CAP) {
        Spans sp = get_spans(g_bodyCell[i]);
        int k = 0;
        for (int base = 0; base < sp.total; base += 32) {
            int c = base + lane;
            bool val = c < sp.total;
            bool P = false;
            int j = -1;
            if (val) {
                float4 b = g_sbody[span_index(sp, c)];
                j = __float_as_int(b.w);
                bool A;
                pair_flags(xi, yi, ri, b.x, b.y, b.z, j == i, A, P);
            }
            unsigned bp = __ballot_sync(FULLM, P);
            if (P) jls[wib][k + __popc(bp & ((1u << lane) - 1u))] = j;
            k += __popc(bp);
        }
        __syncwarp();
        if (lane == 0) {        // sort ascending j -> row-major within-row order
            for (int a = 1; a < k; a++) {
                int v = jls[wib][a];
                int b = a - 1;
                while (b >= 0 && jls[wib][b] > v) { jls[wib][b + 1] = jls[wib][b]; b--; }
                jls[wib][b + 1] = v;
            }
        }
        __syncwarp();
        for (int a = lane; a < k; a += 32) {
            int slot = baseE + a;
            if (slot < KE) {
                int j = jls[wib][a];
                float xj = pos[2 * j], yj = pos[2 * j + 1];
                emit_pair(slot, i, j, xi, yi, ri, xj, yj, rad[j]);
            }
        }
    } else {
        // rare overflow: warp-strided ordered brute scan (j order preserved)
        int rank = 0;
        for (int j0 = 0; j0 < NB; j0 += 32) {
            int j = j0 + lane;
            float xj = pos[2 * j], yj = pos[2 * j + 1], rj = rad[j];
            bool A; bool P;
            pair_flags(xi, yi, ri, xj, yj, rj, j == i, A, P);
            unsigned bp = __ballot_sync(FULLM, P);
            if (P) {
                int slot = baseE + rank + __popc(bp & ((1u << lane) - 1u));
                if (slot < KE)
                    emit_pair(slot, i, j, xi, yi, ri, xj, yj, rj);
            }
            rank += __popc(bp);
        }
    }
}

// ------------------- K6: resolve (also restores g_winner = 0) -----------------
__global__ void k_resolve(const float* __restrict__ pos, float* __restrict__ out) {
    int i = blockIdx.x * blockDim.x + threadIdx.x;
    if (i >= NB) return;
    float x = pos[2 * i];
    float y = pos[2 * i + 1];
    int w = atomicExch(&g_winner[i], 0);     // read + restore in one op
    if (w > KE) {                            // j-write wins
        int k = w - KE - 1;
        x = __fsub_rn(x, __fmul_rn(0.5f, g_evx[k]));
        y = __fsub_rn(y, __fmul_rn(0.5f, g_evy[k]));
    } else if (w > 0) {                      // i-write wins
        int k = w - 1;
        x = __fadd_rn(x, __fmul_rn(0.5f, g_evx[k]));
        y = __fadd_rn(y, __fmul_rn(0.5f, g_evy[k]));
    }
    out[2 * i]     = x;
    out[2 * i + 1] = y;
}

extern "C" void kernel_launch(void* const* d_in, const int* in_sizes, int n_in,
                              void* d_out, int out_size) {
    const float* pos;
    const float* rad;
    if (in_sizes[0] == 2 * NB) { pos = (const float*)d_in[0]; rad = (const float*)d_in[1]; }
    else                       { pos = (const float*)d_in[1]; rad = (const float*)d_in[0]; }
    float* out = (float*)d_out;

    cudaFuncSetAttribute(k_build, cudaFuncAttributeMaxDynamicSharedMemorySize,
                         NCELLS * (int)sizeof(int));

    k_cellcount <<<16,  256>>>(pos);
    k_build     <<<1,   1024, NCELLS * sizeof(int)>>>(pos, rad);
    k_rowcount  <<<512, 256>>>(pos, rad);
    k_scan      <<<1,   1024>>>(pos, rad);
    k_emit      <<<512, 256>>>(pos, rad);
    k_resolve   <<<16,  256>>>(pos, out);
}